// round 3
// baseline (speedup 1.0000x reference)
#include <cuda_runtime.h>
#include <cuda_bf16.h>
#include <math.h>

// Problem constants (fixed by setup_inputs)
#define Bz   2
#define C    64
#define H    128
#define W    128
#define OUT  256
#define TILE 64          // pixels per block (one row segment)
#define NTHR 256

// smem layout (in floats)
#define OFF_W1   0        // w1s[c*68+i],   64x68 = 4352
#define OFF_W2   4352     // w2s[c*68+i],   64x68 = 4352 (only 64 cols valid)
#define OFF_WC   8704     // wcp[(e*8+d)*68+c], 32x68 = 2176
#define OFF_WE   10880    // wes[(e*64+c)*8+d], 2048 (original layout)
#define OFF_WR   12928    // wrs[e*68+i],   4x68 = 272
#define OFF_WO   13200    // wos[o*68+i],   2x68 = 136
#define OFF_B1   13336    // 64
#define OFF_B2   13400    // 64
#define OFF_BR   13464    // 4
#define OFF_BO   13468    // 2 (+pad)
#define OFF_INP  13472    // inps[p*76+i], 64x76 = 4864 (aliased: embs[p*68+i])
#define OFF_HID  18336    // hidden[p*68+c] / fea0[p*68+c], 64x68 = 4352
#define OFF_RS   22688    // rs[p*8+e], 512
#define OFF_OFS  23200    // offs[p*2+o], 128
#define OFF_CMP  23328    // cmps[p*12+d], 768
#define SMEM_FLOATS 24096
#define SMEM_BYTES (SMEM_FLOATS * 4)

#define INP_S 76
#define EMB_S 68
#define FEA_S 68

typedef unsigned long long u64t;

__device__ __forceinline__ u64t fma2(u64t a, u64t b, u64t c) {
    u64t d;
    asm("fma.rn.f32x2 %0, %1, %2, %3;" : "=l"(d) : "l"(a), "l"(b), "l"(c));
    return d;
}
__device__ __forceinline__ float hadd2(u64t v) {
    float lo, hi;
    asm("mov.b64 {%0, %1}, %2;" : "=f"(lo), "=f"(hi) : "l"(v));
    return lo + hi;
}
__device__ __forceinline__ float4 ld4(const float* p) {
    return *reinterpret_cast<const float4*>(p);
}
__device__ __forceinline__ ulonglong2 ld2u(const float* p) {
    return *reinterpret_cast<const ulonglong2*>(p);
}

__device__ __forceinline__ float bilin(const float* __restrict__ img, float fx, float fy) {
    float x0f = floorf(fx), y0f = floorf(fy);
    float wx1 = fx - x0f, wy1 = fy - y0f;
    float wx0 = 1.0f - wx1, wy0 = 1.0f - wy1;
    int x0 = (int)x0f, y0 = (int)y0f;
    int xi0 = min(max(x0, 0), W - 1), yi0 = min(max(y0, 0), H - 1);
    int xi1 = min(max(x0 + 1, 0), W - 1), yi1 = min(max(y0 + 1, 0), H - 1);
    bool vx0 = (x0f >= 0.0f) && (x0f <= (float)(W - 1));
    bool vx1 = (x0f >= -1.0f) && (x0f <= (float)(W - 2));
    bool vy0 = (y0f >= 0.0f) && (y0f <= (float)(H - 1));
    bool vy1 = (y0f >= -1.0f) && (y0f <= (float)(H - 2));
    float v00 = (vx0 && vy0) ? __ldg(img + yi0 * W + xi0) : 0.0f;
    float v10 = (vx1 && vy0) ? __ldg(img + yi0 * W + xi1) : 0.0f;
    float v01 = (vx0 && vy1) ? __ldg(img + yi1 * W + xi0) : 0.0f;
    float v11 = (vx1 && vy1) ? __ldg(img + yi1 * W + xi1) : 0.0f;
    return v00 * (wx0 * wy0) + v10 * (wx1 * wy0) + v01 * (wx0 * wy1) + v11 * (wx1 * wy1);
}

__global__ __launch_bounds__(NTHR, 2)
void SCAB_upsample_20650202759886_kernel(
    const float* __restrict__ x,
    const float* __restrict__ wcmp,   // (4,8,64)
    const float* __restrict__ wexp,   // (4,64,8)
    const float* __restrict__ w1,     // (64,68)
    const float* __restrict__ b1,
    const float* __restrict__ w2,     // (64,64)
    const float* __restrict__ b2,
    const float* __restrict__ wr,     // (4,64)
    const float* __restrict__ br,
    const float* __restrict__ wo,     // (2,64)
    const float* __restrict__ bo,
    float* __restrict__ out)
{
    extern __shared__ float sm[];
    float* w1s  = sm + OFF_W1;
    float* w2s  = sm + OFF_W2;
    float* wcp  = sm + OFF_WC;
    float* wes  = sm + OFF_WE;
    float* wrs  = sm + OFF_WR;
    float* wos  = sm + OFF_WO;
    float* b1s  = sm + OFF_B1;
    float* b2s  = sm + OFF_B2;
    float* brs  = sm + OFF_BR;
    float* bos  = sm + OFF_BO;
    float* inps = sm + OFF_INP;   // also embs (stride 68) after phase 3
    float* embs = sm + OFF_INP;
    float* hidf = sm + OFF_HID;   // hidden / fea0 union (stride 68)
    float* rs   = sm + OFF_RS;
    float* offs = sm + OFF_OFS;
    float* cmps = sm + OFF_CMP;

    const int t  = threadIdx.x;
    const int oy = blockIdx.y;
    const int bz = blockIdx.z;
    const int ox0 = blockIdx.x * TILE;
    const int wid  = t >> 5;      // warp id 0..7
    const int lane = t & 31;

    // ---- stage weights ----
    for (int i = t; i < 64 * 68; i += NTHR) w1s[i] = w1[i];
    for (int i = t; i < 64 * 64; i += NTHR) { int c = i >> 6, k = i & 63; w2s[c * 68 + k] = w2[i]; }
    for (int i = t; i < 32 * 64; i += NTHR) { int ed = i >> 6, c = i & 63; wcp[ed * 68 + c] = wcmp[i]; }
    for (int i = t; i < 2048;    i += NTHR) wes[i] = wexp[i];
    if (t < 256) { int e = t >> 6, k = t & 63; wrs[e * 68 + k] = wr[t]; }
    if (t < 128) { int o = t >> 6, k = t & 63; wos[o * 68 + k] = wo[t]; }
    if (t < 64) { b1s[t] = b1[t]; b2s[t] = b2[t]; }
    if (t < 4) brs[t] = br[t];
    if (t < 2) bos[t] = bo[t];
    __syncthreads();

    const float inv127 = 2.0f / 127.0f;

    // ---- phase 1: coords + pre_fea sample -> inps (stride 76) ----
    {
        const int p  = t & 63;
        const int cb = t >> 6;
        const int ox = ox0 + p;
        float gx = ((ox + 0.5f) / 2.0f - 0.5f) * inv127 - 1.0f;
        float gy = ((oy + 0.5f) / 2.0f - 0.5f) * inv127 - 1.0f;
        float fx = ((gx + 1.0f) * (float)W - 1.0f) * 0.5f;
        float fy = ((gy + 1.0f) * (float)H - 1.0f) * 0.5f;
        if (cb == 0) {
            float ah = (oy + 0.5f) / 2.0f;
            float aw = (ox + 0.5f) / 2.0f;
            *reinterpret_cast<float4*>(&inps[p * INP_S]) =
                make_float4(0.5f, 0.5f,
                            ah - floorf(ah + 0.001f) - 0.5f,
                            aw - floorf(aw + 0.001f) - 0.5f);
        }
        const float* xb = x + (size_t)bz * C * H * W;
        #pragma unroll 1
        for (int k4 = 0; k4 < 4; k4++) {
            float4 v;
            #pragma unroll
            for (int kk = 0; kk < 4; kk++) {
                int c = cb * 16 + k4 * 4 + kk;
                ((float*)&v)[kk] = bilin(xb + c * (H * W), fx, fy);
            }
            *reinterpret_cast<float4*>(&inps[p * INP_S + 4 + cb * 16 + k4 * 4]) = v;
        }
    }
    __syncthreads();

    // ---- phase 2: layer1 (68 -> 64), relu. warp = 8-channel group, lane = 2 px ----
    {
        const int g = wid;             // channel group (8 channels)
        ulonglong2 A0[17], A1[17];
        #pragma unroll
        for (int i = 0; i < 17; i++) {
            A0[i] = ld2u(&inps[lane * INP_S + i * 4]);
            A1[i] = ld2u(&inps[(lane + 32) * INP_S + i * 4]);
        }
        const float* wbase = w1s + g * 8 * 68;
        const float* bb    = b1s + g * 8;
        #pragma unroll 1
        for (int half = 0; half < 2; half++) {
            float4 o0, o1;
            #pragma unroll
            for (int c4 = 0; c4 < 4; c4++) {
                const float* wrow = wbase + (half * 4 + c4) * 68;
                u64t p0a = 0ull, p0b = 0ull, p1a = 0ull, p1b = 0ull;
                #pragma unroll
                for (int i = 0; i < 17; i++) {
                    ulonglong2 wv = ld2u(wrow + i * 4);
                    p0a = fma2(wv.x, A0[i].x, p0a);
                    p0b = fma2(wv.y, A0[i].y, p0b);
                    p1a = fma2(wv.x, A1[i].x, p1a);
                    p1b = fma2(wv.y, A1[i].y, p1b);
                }
                float bv = bb[half * 4 + c4];
                ((float*)&o0)[c4] = fmaxf(hadd2(p0a) + hadd2(p0b) + bv, 0.0f);
                ((float*)&o1)[c4] = fmaxf(hadd2(p1a) + hadd2(p1b) + bv, 0.0f);
            }
            *reinterpret_cast<float4*>(&hidf[lane * 68 + g * 8 + half * 4]) = o0;
            *reinterpret_cast<float4*>(&hidf[(lane + 32) * 68 + g * 8 + half * 4]) = o1;
        }
    }
    __syncthreads();

    // ---- phase 3: layer2 (64 -> 64), relu -> embs (stride 68, aliases inps) ----
    {
        const int g = wid;
        ulonglong2 A0[16], A1[16];
        #pragma unroll
        for (int i = 0; i < 16; i++) {
            A0[i] = ld2u(&hidf[lane * 68 + i * 4]);
            A1[i] = ld2u(&hidf[(lane + 32) * 68 + i * 4]);
        }
        const float* wbase = w2s + g * 8 * 68;
        const float* bb    = b2s + g * 8;
        #pragma unroll 1
        for (int half = 0; half < 2; half++) {
            float4 o0, o1;
            #pragma unroll
            for (int c4 = 0; c4 < 4; c4++) {
                const float* wrow = wbase + (half * 4 + c4) * 68;
                u64t p0a = 0ull, p0b = 0ull, p1a = 0ull, p1b = 0ull;
                #pragma unroll
                for (int i = 0; i < 16; i++) {
                    ulonglong2 wv = ld2u(wrow + i * 4);
                    p0a = fma2(wv.x, A0[i].x, p0a);
                    p0b = fma2(wv.y, A0[i].y, p0b);
                    p1a = fma2(wv.x, A1[i].x, p1a);
                    p1b = fma2(wv.y, A1[i].y, p1b);
                }
                float bv = bb[half * 4 + c4];
                ((float*)&o0)[c4] = fmaxf(hadd2(p0a) + hadd2(p0b) + bv, 0.0f);
                ((float*)&o1)[c4] = fmaxf(hadd2(p1a) + hadd2(p1b) + bv, 0.0f);
            }
            // embs aliases inps; all inps reads finished at the sync above
            *reinterpret_cast<float4*>(&embs[lane * EMB_S + g * 8 + half * 4]) = o0;
            *reinterpret_cast<float4*>(&embs[(lane + 32) * EMB_S + g * 8 + half * 4]) = o1;
        }
    }
    __syncthreads();

    // ---- phase 4: r (sigmoid) + offsets, f32x2 ----
    {
        const int p = t >> 2, e = t & 3;
        const float* erow = &embs[p * EMB_S];
        const float* wrr = wrs + e * 68;
        const float* wor = wos + (e & 1) * 68;
        u64t r0 = 0ull, r1 = 0ull, o0 = 0ull, o1 = 0ull;
        #pragma unroll
        for (int i = 0; i < 16; i++) {
            ulonglong2 ev  = ld2u(erow + i * 4);
            ulonglong2 wrv = ld2u(wrr + i * 4);
            ulonglong2 wov = ld2u(wor + i * 4);
            r0 = fma2(wrv.x, ev.x, r0);
            r1 = fma2(wrv.y, ev.y, r1);
            o0 = fma2(wov.x, ev.x, o0);
            o1 = fma2(wov.y, ev.y, o1);
        }
        float accR = hadd2(r0) + hadd2(r1) + brs[e];
        rs[p * 8 + e] = 1.0f / (1.0f + __expf(-accR));
        if (e < 2) offs[p * 2 + e] = hadd2(o0) + hadd2(o1) + bos[e];
    }
    __syncthreads();

    // ---- phase 5: fea0 sample (with offsets) -> hidf (stride 68) ----
    {
        const int p  = t & 63;
        const int cb = t >> 6;
        const int ox = ox0 + p;
        float gx = ((ox + 0.5f) / 2.0f - 0.5f) * inv127 - 1.0f;
        float gy = ((oy + 0.5f) / 2.0f - 0.5f) * inv127 - 1.0f;
        float ix = gx + offs[p * 2 + 0] * inv127;
        float iy = gy + offs[p * 2 + 1] * inv127;
        float fx = ((ix + 1.0f) * (float)W - 1.0f) * 0.5f;
        float fy = ((iy + 1.0f) * (float)H - 1.0f) * 0.5f;
        const float* xb = x + (size_t)bz * C * H * W;
        #pragma unroll 1
        for (int k4 = 0; k4 < 4; k4++) {
            float4 v;
            #pragma unroll
            for (int kk = 0; kk < 4; kk++) {
                int c = cb * 16 + k4 * 4 + kk;
                ((float*)&v)[kk] = bilin(xb + c * (H * W), fx, fy);
            }
            *reinterpret_cast<float4*>(&hidf[p * FEA_S + cb * 16 + k4 * 4]) = v;
        }
    }
    __syncthreads();

    // ---- phase 6: comp[d] = sum_e r_e * (wc[e,d,:]·fea0). warp = d, lane = 2 px ----
    {
        const int d = wid;
        ulonglong2 F0[16], F1[16];
        #pragma unroll
        for (int i = 0; i < 16; i++) {
            F0[i] = ld2u(&hidf[lane * FEA_S + i * 4]);
            F1[i] = ld2u(&hidf[(lane + 32) * FEA_S + i * 4]);
        }
        float4 rv0 = ld4(&rs[lane * 8]);
        float4 rv1 = ld4(&rs[(lane + 32) * 8]);
        float comp0 = 0.0f, comp1 = 0.0f;
        #pragma unroll
        for (int e = 0; e < 4; e++) {
            const float* wrow = &wcp[(e * 8 + d) * 68];
            u64t a0 = 0ull, a1 = 0ull, c0 = 0ull, c1 = 0ull;
            #pragma unroll
            for (int i = 0; i < 16; i++) {
                ulonglong2 wv = ld2u(wrow + i * 4);
                a0 = fma2(wv.x, F0[i].x, a0);
                a1 = fma2(wv.y, F0[i].y, a1);
                c0 = fma2(wv.x, F1[i].x, c0);
                c1 = fma2(wv.y, F1[i].y, c1);
            }
            comp0 = fmaf(((const float*)&rv0)[e], hadd2(a0) + hadd2(a1), comp0);
            comp1 = fmaf(((const float*)&rv1)[e], hadd2(c0) + hadd2(c1), comp1);
        }
        cmps[lane * 12 + d]        = comp0;
        cmps[(lane + 32) * 12 + d] = comp1;
    }
    __syncthreads();

    // ---- phase 7: expand + residual + store. warp = 8-channel group, lane = 2 px ----
    {
        const int g = wid;
        ulonglong2 cA0 = ld2u(&cmps[lane * 12]);
        ulonglong2 cB0 = ld2u(&cmps[lane * 12 + 4]);
        ulonglong2 cA1 = ld2u(&cmps[(lane + 32) * 12]);
        ulonglong2 cB1 = ld2u(&cmps[(lane + 32) * 12 + 4]);
        float4 rv0 = ld4(&rs[lane * 8]);
        float4 rv1 = ld4(&rs[(lane + 32) * 8]);
        ulonglong2 f0a = ld2u(&hidf[lane * FEA_S + g * 8]);
        ulonglong2 f0b = ld2u(&hidf[lane * FEA_S + g * 8 + 4]);
        ulonglong2 f1a = ld2u(&hidf[(lane + 32) * FEA_S + g * 8]);
        ulonglong2 f1b = ld2u(&hidf[(lane + 32) * FEA_S + g * 8 + 4]);
        float fe0[8], fe1[8];
        *reinterpret_cast<ulonglong2*>(&fe0[0]) = f0a;
        *reinterpret_cast<ulonglong2*>(&fe0[4]) = f0b;
        *reinterpret_cast<ulonglong2*>(&fe1[0]) = f1a;
        *reinterpret_cast<ulonglong2*>(&fe1[4]) = f1b;
        const int ox = ox0 + lane;
        float* ob = out + (((size_t)bz * C + g * 8) * OUT + oy) * OUT + ox;
        #pragma unroll
        for (int k = 0; k < 8; k++) {
            int c = g * 8 + k;
            float acc0 = fe0[k];
            float acc1 = fe1[k];
            #pragma unroll
            for (int e = 0; e < 4; e++) {
                const float* werow = &wes[(e * 64 + c) * 8];
                ulonglong2 wv  = ld2u(werow);
                ulonglong2 wv2 = ld2u(werow + 4);
                u64t s0 = fma2(wv.x, cA0.x, 0ull);
                s0 = fma2(wv.y, cA0.y, s0);
                s0 = fma2(wv2.x, cB0.x, s0);
                s0 = fma2(wv2.y, cB0.y, s0);
                u64t s1 = fma2(wv.x, cA1.x, 0ull);
                s1 = fma2(wv.y, cA1.y, s1);
                s1 = fma2(wv2.x, cB1.x, s1);
                s1 = fma2(wv2.y, cB1.y, s1);
                acc0 = fmaf(((const float*)&rv0)[e], hadd2(s0), acc0);
                acc1 = fmaf(((const float*)&rv1)[e], hadd2(s1), acc1);
            }
            ob[(size_t)k * OUT * OUT]      = acc0;
            ob[(size_t)k * OUT * OUT + 32] = acc1;
        }
    }
}

extern "C" void kernel_launch(void* const* d_in, const int* in_sizes, int n_in,
                              void* d_out, int out_size) {
    (void)in_sizes; (void)n_in; (void)out_size;
    const float* x    = (const float*)d_in[0];
    const float* wcmp = (const float*)d_in[1];
    const float* wexp = (const float*)d_in[2];
    const float* w1   = (const float*)d_in[3];
    const float* b1   = (const float*)d_in[4];
    const float* w2   = (const float*)d_in[5];
    const float* b2   = (const float*)d_in[6];
    const float* wr   = (const float*)d_in[7];
    const float* br   = (const float*)d_in[8];
    const float* wo   = (const float*)d_in[9];
    const float* bo   = (const float*)d_in[10];
    float* out = (float*)d_out;

    cudaFuncSetAttribute(SCAB_upsample_20650202759886_kernel,
                         cudaFuncAttributeMaxDynamicSharedMemorySize, SMEM_BYTES);
    dim3 grid(OUT / TILE, OUT, Bz);
    SCAB_upsample_20650202759886_kernel<<<grid, NTHR, SMEM_BYTES>>>(
        x, wcmp, wexp, w1, b1, w2, b2, wr, br, wo, bo, out);
}

// round 4
// speedup vs baseline: 1.1765x; 1.1765x over previous
#include <cuda_runtime.h>
#include <cuda_bf16.h>
#include <math.h>

// Problem constants (fixed by setup_inputs)
#define Bz   2
#define C    64
#define H    128
#define W    128
#define OUT  256
#define TILE 64          // pixels per block (one row segment)
#define NTHR 256

// smem layout (in floats)
#define OFF_W1   0        // w1s[c*68+i],   64x68 = 4352
#define OFF_W2   4352     // w2s[c*68+i],   64x68 = 4352 (only 64 cols valid)
#define OFF_WC   8704     // wcp[(e*8+d)*68+c], 32x68 = 2176
#define OFF_WE   10880    // wes[(e*64+c)*8+d], 2048 (original layout)
#define OFF_WR   12928    // wrs[e*68+i],   4x68 = 272
#define OFF_WO   13200    // wos[o*68+i],   2x68 = 136
#define OFF_B1   13336    // 64
#define OFF_B2   13400    // 64
#define OFF_BR   13464    // 4
#define OFF_BO   13468    // 2 (+pad)
#define OFF_INP  13472    // inps[p*76+i], 64x76 = 4864 (aliased: embs[p*68+i])
#define OFF_HID  18336    // hidden[p*68+c] / fea0[p*68+c], 64x68 = 4352
#define OFF_RS   22688    // rs[p*8+e], 512
#define OFF_OFS  23200    // offs[p*2+o], 128
#define OFF_CMP  23328    // cmps[p*12+d], 768
#define SMEM_FLOATS 24096
#define SMEM_BYTES (SMEM_FLOATS * 4)

#define INP_S 76
#define EMB_S 68
#define FEA_S 68

typedef unsigned long long u64t;

__device__ __forceinline__ u64t fma2(u64t a, u64t b, u64t c) {
    u64t d;
    asm("fma.rn.f32x2 %0, %1, %2, %3;" : "=l"(d) : "l"(a), "l"(b), "l"(c));
    return d;
}
__device__ __forceinline__ u64t add2(u64t a, u64t b) {
    u64t d;
    asm("add.rn.f32x2 %0, %1, %2;" : "=l"(d) : "l"(a), "l"(b));
    return d;
}
__device__ __forceinline__ float hadd2(u64t v) {
    float lo, hi;
    asm("mov.b64 {%0, %1}, %2;" : "=f"(lo), "=f"(hi) : "l"(v));
    return lo + hi;
}
__device__ __forceinline__ float4 ld4(const float* p) {
    return *reinterpret_cast<const float4*>(p);
}
__device__ __forceinline__ ulonglong2 ld2u(const float* p) {
    return *reinterpret_cast<const ulonglong2*>(p);
}

__device__ __forceinline__ float bilin(const float* __restrict__ img, float fx, float fy) {
    float x0f = floorf(fx), y0f = floorf(fy);
    float wx1 = fx - x0f, wy1 = fy - y0f;
    float wx0 = 1.0f - wx1, wy0 = 1.0f - wy1;
    int x0 = (int)x0f, y0 = (int)y0f;
    int xi0 = min(max(x0, 0), W - 1), yi0 = min(max(y0, 0), H - 1);
    int xi1 = min(max(x0 + 1, 0), W - 1), yi1 = min(max(y0 + 1, 0), H - 1);
    bool vx0 = (x0f >= 0.0f) && (x0f <= (float)(W - 1));
    bool vx1 = (x0f >= -1.0f) && (x0f <= (float)(W - 2));
    bool vy0 = (y0f >= 0.0f) && (y0f <= (float)(H - 1));
    bool vy1 = (y0f >= -1.0f) && (y0f <= (float)(H - 2));
    float v00 = (vx0 && vy0) ? __ldg(img + yi0 * W + xi0) : 0.0f;
    float v10 = (vx1 && vy0) ? __ldg(img + yi0 * W + xi1) : 0.0f;
    float v01 = (vx0 && vy1) ? __ldg(img + yi1 * W + xi0) : 0.0f;
    float v11 = (vx1 && vy1) ? __ldg(img + yi1 * W + xi1) : 0.0f;
    return v00 * (wx0 * wy0) + v10 * (wx1 * wy0) + v01 * (wx0 * wy1) + v11 * (wx1 * wy1);
}

__global__ __launch_bounds__(NTHR, 2)
void SCAB_upsample_20650202759886_kernel(
    const float* __restrict__ x,
    const float* __restrict__ wcmp,   // (4,8,64)
    const float* __restrict__ wexp,   // (4,64,8)
    const float* __restrict__ w1,     // (64,68)
    const float* __restrict__ b1,
    const float* __restrict__ w2,     // (64,64)
    const float* __restrict__ b2,
    const float* __restrict__ wr,     // (4,64)
    const float* __restrict__ br,
    const float* __restrict__ wo,     // (2,64)
    const float* __restrict__ bo,
    float* __restrict__ out)
{
    extern __shared__ float sm[];
    float* w1s  = sm + OFF_W1;
    float* w2s  = sm + OFF_W2;
    float* wcp  = sm + OFF_WC;
    float* wes  = sm + OFF_WE;
    float* wrs  = sm + OFF_WR;
    float* wos  = sm + OFF_WO;
    float* b1s  = sm + OFF_B1;
    float* b2s  = sm + OFF_B2;
    float* brs  = sm + OFF_BR;
    float* bos  = sm + OFF_BO;
    float* inps = sm + OFF_INP;   // also embs (stride 68) after phase 3
    float* embs = sm + OFF_INP;
    float* hidf = sm + OFF_HID;   // hidden / fea0 union (stride 68)
    float* rs   = sm + OFF_RS;
    float* offs = sm + OFF_OFS;
    float* cmps = sm + OFF_CMP;

    const int t  = threadIdx.x;
    const int oy = blockIdx.y;
    const int bz = blockIdx.z;
    const int ox0 = blockIdx.x * TILE;
    const int wid  = t >> 5;
    const int lane = t & 31;

    // ---- stage weights ----
    for (int i = t; i < 64 * 68; i += NTHR) w1s[i] = w1[i];
    for (int i = t; i < 64 * 64; i += NTHR) { int c = i >> 6, k = i & 63; w2s[c * 68 + k] = w2[i]; }
    for (int i = t; i < 32 * 64; i += NTHR) { int ed = i >> 6, c = i & 63; wcp[ed * 68 + c] = wcmp[i]; }
    for (int i = t; i < 2048;    i += NTHR) wes[i] = wexp[i];
    if (t < 256) { int e = t >> 6, k = t & 63; wrs[e * 68 + k] = wr[t]; }
    if (t < 128) { int o = t >> 6, k = t & 63; wos[o * 68 + k] = wo[t]; }
    if (t < 64) { b1s[t] = b1[t]; b2s[t] = b2[t]; }
    if (t < 4) brs[t] = br[t];
    if (t < 2) bos[t] = bo[t];
    __syncthreads();

    const float inv127 = 2.0f / 127.0f;

    // ---- phase 1: coords + pre_fea sample -> inps (stride 76), vector stores ----
    {
        const int p  = t & 63;
        const int cb = t >> 6;
        const int ox = ox0 + p;
        float gx = ((ox + 0.5f) / 2.0f - 0.5f) * inv127 - 1.0f;
        float gy = ((oy + 0.5f) / 2.0f - 0.5f) * inv127 - 1.0f;
        float fx = ((gx + 1.0f) * (float)W - 1.0f) * 0.5f;
        float fy = ((gy + 1.0f) * (float)H - 1.0f) * 0.5f;
        if (cb == 0) {
            float ah = (oy + 0.5f) / 2.0f;
            float aw = (ox + 0.5f) / 2.0f;
            *reinterpret_cast<float4*>(&inps[p * INP_S]) =
                make_float4(0.5f, 0.5f,
                            ah - floorf(ah + 0.001f) - 0.5f,
                            aw - floorf(aw + 0.001f) - 0.5f);
        }
        const float* xb = x + (size_t)bz * C * H * W;
        #pragma unroll 1
        for (int k4 = 0; k4 < 4; k4++) {
            float4 v;
            #pragma unroll
            for (int kk = 0; kk < 4; kk++) {
                int c = cb * 16 + k4 * 4 + kk;
                ((float*)&v)[kk] = bilin(xb + c * (H * W), fx, fy);
            }
            *reinterpret_cast<float4*>(&inps[p * INP_S + 4 + cb * 16 + k4 * 4]) = v;
        }
    }
    __syncthreads();

    // ---- phase 2: layer1 (68 -> 64), relu. thread = (pixel, 16-ch group) ----
    {
        const int p = t & 63, g = t >> 6;
        ulonglong2 A[17];
        #pragma unroll
        for (int i = 0; i < 17; i++) A[i] = ld2u(&inps[p * INP_S + i * 4]);
        const float* wbase = w1s + g * 16 * 68;
        const float* bb    = b1s + g * 16;
        float* hrow = &hidf[p * 68 + g * 16];
        #pragma unroll 1
        for (int cc = 0; cc < 4; cc++) {
            float4 o4;
            #pragma unroll
            for (int c4 = 0; c4 < 4; c4++) {
                const float* wrow = wbase + (cc * 4 + c4) * 68;
                u64t a0 = 0ull, a1 = 0ull;
                #pragma unroll
                for (int i = 0; i < 17; i++) {
                    ulonglong2 wv = ld2u(wrow + i * 4);
                    a0 = fma2(wv.x, A[i].x, a0);
                    a1 = fma2(wv.y, A[i].y, a1);
                }
                float s = hadd2(add2(a0, a1)) + bb[cc * 4 + c4];
                ((float*)&o4)[c4] = fmaxf(s, 0.0f);
            }
            *reinterpret_cast<float4*>(hrow + cc * 4) = o4;
        }
    }
    __syncthreads();

    // ---- phase 3: layer2 (64 -> 64), relu -> embs (stride 68, aliases inps) ----
    {
        const int p = t & 63, g = t >> 6;
        ulonglong2 A[16];
        #pragma unroll
        for (int i = 0; i < 16; i++) A[i] = ld2u(&hidf[p * 68 + i * 4]);
        const float* wbase = w2s + g * 16 * 68;
        const float* bb    = b2s + g * 16;
        float erow[16];
        #pragma unroll 1
        for (int cc = 0; cc < 4; cc++) {
            #pragma unroll
            for (int c4 = 0; c4 < 4; c4++) {
                const float* wrow = wbase + (cc * 4 + c4) * 68;
                u64t a0 = 0ull, a1 = 0ull;
                #pragma unroll
                for (int i = 0; i < 16; i++) {
                    ulonglong2 wv = ld2u(wrow + i * 4);
                    a0 = fma2(wv.x, A[i].x, a0);
                    a1 = fma2(wv.y, A[i].y, a1);
                }
                float s = hadd2(add2(a0, a1)) + bb[cc * 4 + c4];
                erow[cc * 4 + c4] = fmaxf(s, 0.0f);
            }
        }
        // embs aliases inps; all inps reads finished at the sync above
        float* ebase = &embs[p * EMB_S + g * 16];
        #pragma unroll
        for (int cc = 0; cc < 4; cc++)
            *reinterpret_cast<float4*>(ebase + cc * 4) =
                *reinterpret_cast<const float4*>(&erow[cc * 4]);
    }
    __syncthreads();

    // ---- phase 4: r (sigmoid) + offsets, f32x2 ----
    {
        const int p = t >> 2, e = t & 3;
        const float* erow = &embs[p * EMB_S];
        const float* wrr = wrs + e * 68;
        const float* wor = wos + (e & 1) * 68;
        u64t r0 = 0ull, r1 = 0ull, o0 = 0ull, o1 = 0ull;
        #pragma unroll
        for (int i = 0; i < 16; i++) {
            ulonglong2 ev  = ld2u(erow + i * 4);
            ulonglong2 wrv = ld2u(wrr + i * 4);
            ulonglong2 wov = ld2u(wor + i * 4);
            r0 = fma2(wrv.x, ev.x, r0);
            r1 = fma2(wrv.y, ev.y, r1);
            o0 = fma2(wov.x, ev.x, o0);
            o1 = fma2(wov.y, ev.y, o1);
        }
        float accR = hadd2(add2(r0, r1)) + brs[e];
        rs[p * 8 + e] = 1.0f / (1.0f + __expf(-accR));
        if (e < 2) offs[p * 2 + e] = hadd2(add2(o0, o1)) + bos[e];
    }
    __syncthreads();

    // ---- phase 5: fea0 sample (with offsets) -> hidf (stride 68), vector stores ----
    {
        const int p  = t & 63;
        const int cb = t >> 6;
        const int ox = ox0 + p;
        float gx = ((ox + 0.5f) / 2.0f - 0.5f) * inv127 - 1.0f;
        float gy = ((oy + 0.5f) / 2.0f - 0.5f) * inv127 - 1.0f;
        float ix = gx + offs[p * 2 + 0] * inv127;
        float iy = gy + offs[p * 2 + 1] * inv127;
        float fx = ((ix + 1.0f) * (float)W - 1.0f) * 0.5f;
        float fy = ((iy + 1.0f) * (float)H - 1.0f) * 0.5f;
        const float* xb = x + (size_t)bz * C * H * W;
        #pragma unroll 1
        for (int k4 = 0; k4 < 4; k4++) {
            float4 v;
            #pragma unroll
            for (int kk = 0; kk < 4; kk++) {
                int c = cb * 16 + k4 * 4 + kk;
                ((float*)&v)[kk] = bilin(xb + c * (H * W), fx, fy);
            }
            *reinterpret_cast<float4*>(&hidf[p * FEA_S + cb * 16 + k4 * 4]) = v;
        }
    }
    __syncthreads();

    // ---- phase 6: comp[d] = sum_e r_e * (wc[e,d,:]·fea0).
    //      warp = d (unique weights, broadcast), lane = px, two halves ----
    {
        const int d = wid;
        #pragma unroll 1
        for (int h = 0; h < 2; h++) {
            const int p = h * 32 + lane;
            ulonglong2 F[16];
            #pragma unroll
            for (int i = 0; i < 16; i++) F[i] = ld2u(&hidf[p * FEA_S + i * 4]);
            float4 rv = ld4(&rs[p * 8]);
            float comp = 0.0f;
            #pragma unroll
            for (int e = 0; e < 4; e++) {
                const float* wrow = &wcp[(e * 8 + d) * 68];
                u64t a0 = 0ull, a1 = 0ull;
                #pragma unroll
                for (int i = 0; i < 16; i++) {
                    ulonglong2 wv = ld2u(wrow + i * 4);
                    a0 = fma2(wv.x, F[i].x, a0);
                    a1 = fma2(wv.y, F[i].y, a1);
                }
                comp = fmaf(((const float*)&rv)[e], hadd2(add2(a0, a1)), comp);
            }
            cmps[p * 12 + d] = comp;
        }
    }
    __syncthreads();

    // ---- phase 7: expand + residual + store. thread = (pixel, 16-ch group) ----
    {
        const int p  = t & 63;
        const int cb = t >> 6;
        ulonglong2 cr0 = ld2u(&cmps[p * 12]);
        ulonglong2 cr1 = ld2u(&cmps[p * 12 + 4]);
        float4 rv = ld4(&rs[p * 8]);
        const int ox = ox0 + p;
        float* ob = out + (((size_t)bz * C + cb * 16) * OUT + oy) * OUT + ox;
        #pragma unroll 1
        for (int k4 = 0; k4 < 4; k4++) {
            float4 f4 = ld4(&hidf[p * FEA_S + cb * 16 + k4 * 4]);
            #pragma unroll
            for (int kk = 0; kk < 4; kk++) {
                int c = cb * 16 + k4 * 4 + kk;
                float acc = ((const float*)&f4)[kk];
                #pragma unroll
                for (int e = 0; e < 4; e++) {
                    const float* werow = &wes[(e * 64 + c) * 8];
                    ulonglong2 wv = ld2u(werow);
                    ulonglong2 wv2 = ld2u(werow + 4);
                    u64t s2 = fma2(wv.x, cr0.x, 0ull);
                    s2 = fma2(wv.y, cr0.y, s2);
                    s2 = fma2(wv2.x, cr1.x, s2);
                    s2 = fma2(wv2.y, cr1.y, s2);
                    acc = fmaf(((const float*)&rv)[e], hadd2(s2), acc);
                }
                ob[(size_t)(k4 * 4 + kk) * OUT * OUT] = acc;
            }
        }
    }
}

extern "C" void kernel_launch(void* const* d_in, const int* in_sizes, int n_in,
                              void* d_out, int out_size) {
    (void)in_sizes; (void)n_in; (void)out_size;
    const float* x    = (const float*)d_in[0];
    const float* wcmp = (const float*)d_in[1];
    const float* wexp = (const float*)d_in[2];
    const float* w1   = (const float*)d_in[3];
    const float* b1   = (const float*)d_in[4];
    const float* w2   = (const float*)d_in[5];
    const float* b2   = (const float*)d_in[6];
    const float* wr   = (const float*)d_in[7];
    const float* br   = (const float*)d_in[8];
    const float* wo   = (const float*)d_in[9];
    const float* bo   = (const float*)d_in[10];
    float* out = (float*)d_out;

    cudaFuncSetAttribute(SCAB_upsample_20650202759886_kernel,
                         cudaFuncAttributeMaxDynamicSharedMemorySize, SMEM_BYTES);
    dim3 grid(OUT / TILE, OUT, Bz);
    SCAB_upsample_20650202759886_kernel<<<grid, NTHR, SMEM_BYTES>>>(
        x, wcmp, wexp, w1, b1, w2, b2, wr, br, wo, bo, out);
}